// round 15
// baseline (speedup 1.0000x reference)
#include <cuda_runtime.h>
#include <cuda_bf16.h>
#include <cuda_fp16.h>
#include <cstdint>

// ---------------- problem constants ----------------
#define N_NODES 50000
#define N_EDGES 800000
#define HEADS   4
#define N_GRAPHS 50
#define NEG_SLOPE 0.2f
#define FEAT 256

// ---------------- scratch ----------------
__device__ float    g_bufB[N_NODES * FEAT];   // out1 (relu'd)
__device__ __half   g_h16 [N_NODES * FEAT];   // h1, then h2 (fp16 gather payload)
__device__ float    g_asrc[N_NODES * HEADS];  // layer-1 scores
__device__ float    g_adst[N_NODES * HEADS];
__device__ float    g_asrc2[N_NODES];         // layer-2 scores (H=1)
__device__ float    g_adst2[N_NODES];
__device__ unsigned g_deg [N_NODES];
__device__ unsigned g_rowptr[N_NODES + 1];
__device__ unsigned g_cursor[N_NODES];
__device__ int      g_csrc[N_EDGES];
__device__ unsigned g_bsum[256];
__device__ float    g_psum[N_GRAPHS * FEAT];
__device__ float    g_cnt [N_GRAPHS];
__device__ __nv_bfloat16 g_w1h[FEAT * FEAT], g_w1l[FEAT * FEAT];
__device__ __nv_bfloat16 g_w2h[FEAT * FEAT], g_w2l[FEAT * FEAT];

// ---------------- helpers ----------------
__device__ __forceinline__ float lrelu(float v) { return v >= 0.f ? v : NEG_SLOPE * v; }
__device__ __forceinline__ uint32_t pack_bf2(float a, float b) {
    uint32_t lo = (uint32_t)__bfloat16_as_ushort(__float2bfloat16(a));
    uint32_t hi = (uint32_t)__bfloat16_as_ushort(__float2bfloat16(b));
    return (hi << 16) | lo;
}

// ================= weight convert (both layers, one kernel) ===============
__global__ void conv_w2(const float* __restrict__ W1, const float* __restrict__ W2) {
    int i = blockIdx.x * 256 + threadIdx.x;          // 0..131071
    int j = i & 65535;
    int k = j >> 8, n = j & 255;
    if (i < 65536) {
        float v = W1[j];
        __nv_bfloat16 h = __float2bfloat16(v);
        g_w1h[n * 256 + k] = h;
        g_w1l[n * 256 + k] = __float2bfloat16(v - __bfloat162float(h));
    } else {
        float v = W2[j];
        __nv_bfloat16 h = __float2bfloat16(v);
        g_w2h[n * 256 + k] = h;
        g_w2l[n * 256 + k] = __float2bfloat16(v - __bfloat162float(h));
    }
}

// ================= HMMA GEMM + fused attention-score epilogue =============
__device__ __forceinline__ void mma16816(float* c, const uint32_t* a, const uint32_t* b) {
    asm volatile(
        "mma.sync.aligned.m16n8k16.row.col.f32.bf16.bf16.f32 "
        "{%0,%1,%2,%3}, {%4,%5,%6,%7}, {%8,%9}, {%0,%1,%2,%3};"
        : "+f"(c[0]), "+f"(c[1]), "+f"(c[2]), "+f"(c[3])
        : "r"(a[0]), "r"(a[1]), "r"(a[2]), "r"(a[3]), "r"(b[0]), "r"(b[1]));
}

template <int H>
__global__ void __launch_bounds__(256, 1) gemm_mma(
    const float* __restrict__ A, const __nv_bfloat16* __restrict__ Bh,
    const __nv_bfloat16* __restrict__ Bl, __half* __restrict__ C, int M,
    const float* __restrict__ att_s, const float* __restrict__ att_d,
    float* __restrict__ o_asrc, float* __restrict__ o_adst) {
    extern __shared__ char sm[];
    uint32_t* Ahs = (uint32_t*)sm;                 // 64 KB
    uint32_t* Als = (uint32_t*)(sm + 65536);       // 64 KB

    int t = threadIdx.x;
    int warp = t >> 5, lane = t & 31;
    int g = lane >> 2, tg = lane & 3;
    int m0 = blockIdx.y * 128;
    int n0 = blockIdx.x * 128;

    // ---- stage A (fragment-permuted bf16 hi/lo) ----
    {
        int r0 = m0 + warp * 16 + g;
        int r1 = r0 + 8;
        bool ok0 = r0 < M, ok1 = r1 < M;
        const float* A0 = A + (size_t)r0 * 256 + 2 * tg;
        const float* A1 = A + (size_t)r1 * 256 + 2 * tg;
#pragma unroll
        for (int ks = 0; ks < 16; ks++) {
            float2 f0 = ok0 ? *(const float2*)(A0 + 16 * ks)     : make_float2(0.f, 0.f);
            float2 f1 = ok1 ? *(const float2*)(A1 + 16 * ks)     : make_float2(0.f, 0.f);
            float2 f2 = ok0 ? *(const float2*)(A0 + 16 * ks + 8) : make_float2(0.f, 0.f);
            float2 f3 = ok1 ? *(const float2*)(A1 + 16 * ks + 8) : make_float2(0.f, 0.f);
            float h0x = __bfloat162float(__float2bfloat16(f0.x));
            float h0y = __bfloat162float(__float2bfloat16(f0.y));
            float h1x = __bfloat162float(__float2bfloat16(f1.x));
            float h1y = __bfloat162float(__float2bfloat16(f1.y));
            float h2x = __bfloat162float(__float2bfloat16(f2.x));
            float h2y = __bfloat162float(__float2bfloat16(f2.y));
            float h3x = __bfloat162float(__float2bfloat16(f3.x));
            float h3y = __bfloat162float(__float2bfloat16(f3.y));
            int idx = ((warp * 16 + ks) * 32 + lane) * 4;
            uint4 hv = make_uint4(pack_bf2(f0.x, f0.y), pack_bf2(f1.x, f1.y),
                                  pack_bf2(f2.x, f2.y), pack_bf2(f3.x, f3.y));
            uint4 lv = make_uint4(pack_bf2(f0.x - h0x, f0.y - h0y),
                                  pack_bf2(f1.x - h1x, f1.y - h1y),
                                  pack_bf2(f2.x - h2x, f2.y - h2y),
                                  pack_bf2(f3.x - h3x, f3.y - h3y));
            *(uint4*)(Ahs + idx) = hv;
            *(uint4*)(Als + idx) = lv;
        }
    }
    __syncthreads();

    // ---- mainloop ----
    int wm = warp & 1;
    int wn = warp >> 1;
    float acc[4][4][4];
#pragma unroll
    for (int i = 0; i < 4; i++)
#pragma unroll
        for (int j = 0; j < 4; j++)
#pragma unroll
            for (int q = 0; q < 4; q++) acc[i][j][q] = 0.f;

    const __nv_bfloat16* Bbase[3] = { Bh, Bl, Bh };
#pragma unroll
    for (int pass = 0; pass < 3; pass++) {
        const uint32_t* Asm = (pass == 2) ? Als : Ahs;
        const __nv_bfloat16* Bg = Bbase[pass];
#pragma unroll 4
        for (int ks = 0; ks < 16; ks++) {
            uint32_t b[4][2];
#pragma unroll
            for (int fn = 0; fn < 4; fn++) {
                int n = n0 + wn * 32 + fn * 8 + g;
                const uint32_t* bp = (const uint32_t*)(Bg + (size_t)n * 256 + 16 * ks + 2 * tg);
                b[fn][0] = bp[0];
                b[fn][1] = bp[4];
            }
#pragma unroll
            for (int fm = 0; fm < 4; fm++) {
                int fm_g = wm * 4 + fm;
                uint4 av = *(const uint4*)(Asm + ((fm_g * 16 + ks) * 32 + lane) * 4);
                uint32_t a[4] = { av.x, av.y, av.z, av.w };
#pragma unroll
                for (int fn = 0; fn < 4; fn++)
                    mma16816(acc[fm][fn], a, b[fn]);
            }
        }
    }

    // ---- epilogue: store C as fp16 ----
#pragma unroll
    for (int fm = 0; fm < 4; fm++) {
        int r0 = m0 + wm * 64 + fm * 16 + g;
        int r1 = r0 + 8;
#pragma unroll
        for (int fn = 0; fn < 4; fn++) {
            int col = n0 + wn * 32 + fn * 8 + 2 * tg;
            if (r0 < M)
                *(__half2*)(C + (size_t)r0 * 256 + col) =
                    __floats2half2_rn(acc[fm][fn][0], acc[fm][fn][1]);
            if (r1 < M)
                *(__half2*)(C + (size_t)r1 * 256 + col) =
                    __floats2half2_rn(acc[fm][fn][2], acc[fm][fn][3]);
        }
    }

    // ---- epilogue: fused attention scores (fp32 accumulators) ----
    float2 as2[4], ad2[4];
#pragma unroll
    for (int fn = 0; fn < 4; fn++) {
        int col = n0 + wn * 32 + fn * 8 + 2 * tg;
        as2[fn] = *(const float2*)(att_s + col);
        ad2[fn] = *(const float2*)(att_d + col);
    }
    int head = (H == 4) ? ((n0 + wn * 32) >> 6) : 0;
#pragma unroll
    for (int fm = 0; fm < 4; fm++) {
        int r0 = m0 + wm * 64 + fm * 16 + g;
        int r1 = r0 + 8;
        float s0 = 0.f, d0 = 0.f, s1 = 0.f, d1 = 0.f;
#pragma unroll
        for (int fn = 0; fn < 4; fn++) {
            s0 += acc[fm][fn][0] * as2[fn].x + acc[fm][fn][1] * as2[fn].y;
            d0 += acc[fm][fn][0] * ad2[fn].x + acc[fm][fn][1] * ad2[fn].y;
            s1 += acc[fm][fn][2] * as2[fn].x + acc[fm][fn][3] * as2[fn].y;
            d1 += acc[fm][fn][2] * ad2[fn].x + acc[fm][fn][3] * ad2[fn].y;
        }
#pragma unroll
        for (int o = 1; o <= 2; o <<= 1) {
            s0 += __shfl_xor_sync(0xffffffffu, s0, o);
            d0 += __shfl_xor_sync(0xffffffffu, d0, o);
            s1 += __shfl_xor_sync(0xffffffffu, s1, o);
            d1 += __shfl_xor_sync(0xffffffffu, d1, o);
        }
        if (tg == 0) {
            if (r0 < M) {
                atomicAdd(&o_asrc[r0 * H + head], s0);
                atomicAdd(&o_adst[r0 * H + head], d0);
            }
            if (r1 < M) {
                atomicAdd(&o_asrc[r1 * H + head], s1);
                atomicAdd(&o_adst[r1 * H + head], d1);
            }
        }
    }
}

// ================= CSR build ==============================================
__global__ void zero_misc() {
    int i = blockIdx.x * 256 + threadIdx.x;
    if (i < N_NODES) { g_deg[i] = 0u; g_asrc2[i] = 0.f; g_adst2[i] = 0.f; }
    if (i < N_NODES * HEADS) { g_asrc[i] = 0.f; g_adst[i] = 0.f; }
    if (i < N_GRAPHS * FEAT) g_psum[i] = 0.f;
    if (i < N_GRAPHS) g_cnt[i] = 0.f;
}
__global__ void hist_plus(const int* __restrict__ dst, const int* __restrict__ batch) {
    int i = blockIdx.x * 256 + threadIdx.x;
    if (i < N_EDGES) atomicAdd(&g_deg[dst[i]], 1u);
    if (i < N_NODES) atomicAdd(&g_cnt[batch[i]], 1.0f);
}
__global__ void scan1() {
    __shared__ unsigned s[256];
    int t = threadIdx.x, i = blockIdx.x * 256 + t;
    unsigned v = (i < N_NODES) ? g_deg[i] : 0u;
    s[t] = v; __syncthreads();
#pragma unroll
    for (int o = 1; o < 256; o <<= 1) {
        unsigned u = (t >= o) ? s[t - o] : 0u;
        __syncthreads();
        s[t] += u; __syncthreads();
    }
    if (i < N_NODES) g_rowptr[i + 1] = s[t];
    if (t == 255) g_bsum[blockIdx.x] = s[255];
}
__global__ void scan2(int nb) {
    __shared__ unsigned s[256];
    int t = threadIdx.x;
    unsigned v = (t < nb) ? g_bsum[t] : 0u;
    s[t] = v; __syncthreads();
#pragma unroll
    for (int o = 1; o < 256; o <<= 1) {
        unsigned u = (t >= o) ? s[t - o] : 0u;
        __syncthreads();
        s[t] += u; __syncthreads();
    }
    if (t < nb) g_bsum[t] = s[t] - v;                // exclusive
}
__global__ void scan3() {
    int i = blockIdx.x * 256 + threadIdx.x;
    if (i >= N_NODES) return;
    unsigned f = g_rowptr[i + 1] + g_bsum[i >> 8];
    g_rowptr[i + 1] = f;
    g_cursor[i] = f - g_deg[i];
    if (i == 0) g_rowptr[0] = 0u;
}
__global__ void scatter(const int* __restrict__ src, const int* __restrict__ dst) {
    int e = blockIdx.x * 256 + threadIdx.x;
    if (e >= N_EDGES) return;
    unsigned p = atomicAdd(&g_cursor[dst[e]], 1u);
    g_csrc[p] = src[e];
}

// ================= fused single-pass GAT aggregation ======================
// out[w] = relu( (sum_e ex_e * h[src_e]) / (sum_e ex_e) + bias )
// 4-edge unrolled for MLP; POOL=true skips the out write and atomically
// accumulates the row into g_psum[batch[w]] (mean-pool fusion).
template <int H, bool POOL>
__global__ void gat_gather(const __half* __restrict__ h, float* __restrict__ out,
                           const float* __restrict__ bias,
                           const float* __restrict__ v_asrc,
                           const float* __restrict__ v_adst,
                           const int* __restrict__ batch) {
    int w = (blockIdx.x * blockDim.x + threadIdx.x) >> 5;
    int lane = threadIdx.x & 31;
    if (w >= N_NODES) return;
    int r0 = (int)g_rowptr[w], r1 = (int)g_rowptr[w + 1];
    int ch = lane * 8;
    int hh = (H == 4) ? (lane >> 3) : 0;
    float4 b0 = *(const float4*)(bias + ch);
    float4 b1 = *(const float4*)(bias + ch + 4);
    float r_out[8];
    if (r0 == r1) {
        r_out[0] = fmaxf(b0.x, 0.f); r_out[1] = fmaxf(b0.y, 0.f);
        r_out[2] = fmaxf(b0.z, 0.f); r_out[3] = fmaxf(b0.w, 0.f);
        r_out[4] = fmaxf(b1.x, 0.f); r_out[5] = fmaxf(b1.y, 0.f);
        r_out[6] = fmaxf(b1.z, 0.f); r_out[7] = fmaxf(b1.w, 0.f);
    } else {
        float ad_h = v_adst[w * H + hh];
        float acc[8];
#pragma unroll
        for (int q = 0; q < 8; q++) acc[q] = 0.f;
        float sum_ex = 0.f;
        int e = r0;
        for (; e + 3 < r1; e += 4) {
            int s0 = g_csrc[e],     s1 = g_csrc[e + 1];
            int s2 = g_csrc[e + 2], s3 = g_csrc[e + 3];
            float a0 = v_asrc[s0 * H + hh], a1 = v_asrc[s1 * H + hh];
            float a2 = v_asrc[s2 * H + hh], a3 = v_asrc[s3 * H + hh];
            uint4 v0 = *(const uint4*)(h + (size_t)s0 * FEAT + ch);
            uint4 v1 = *(const uint4*)(h + (size_t)s1 * FEAT + ch);
            uint4 v2 = *(const uint4*)(h + (size_t)s2 * FEAT + ch);
            uint4 v3 = *(const uint4*)(h + (size_t)s3 * FEAT + ch);
            float e0 = __expf(lrelu(a0 + ad_h));
            float e1 = __expf(lrelu(a1 + ad_h));
            float e2 = __expf(lrelu(a2 + ad_h));
            float e3 = __expf(lrelu(a3 + ad_h));
            sum_ex += (e0 + e1) + (e2 + e3);
            const __half2* p0 = (const __half2*)&v0;
            const __half2* p1 = (const __half2*)&v1;
            const __half2* p2 = (const __half2*)&v2;
            const __half2* p3 = (const __half2*)&v3;
#pragma unroll
            for (int q = 0; q < 4; q++) {
                float2 f0 = __half22float2(p0[q]);
                float2 f1 = __half22float2(p1[q]);
                float2 f2 = __half22float2(p2[q]);
                float2 f3 = __half22float2(p3[q]);
                acc[2 * q + 0] = fmaf(e0, f0.x, fmaf(e1, f1.x,
                                 fmaf(e2, f2.x, fmaf(e3, f3.x, acc[2 * q + 0]))));
                acc[2 * q + 1] = fmaf(e0, f0.y, fmaf(e1, f1.y,
                                 fmaf(e2, f2.y, fmaf(e3, f3.y, acc[2 * q + 1]))));
            }
        }
        for (; e < r1; e++) {
            int s = g_csrc[e];
            float ex = __expf(lrelu(v_asrc[s * H + hh] + ad_h));
            sum_ex += ex;
            uint4 v = *(const uint4*)(h + (size_t)s * FEAT + ch);
            const __half2* hv = (const __half2*)&v;
#pragma unroll
            for (int q = 0; q < 4; q++) {
                float2 f = __half22float2(hv[q]);
                acc[2 * q + 0] = fmaf(ex, f.x, acc[2 * q + 0]);
                acc[2 * q + 1] = fmaf(ex, f.y, acc[2 * q + 1]);
            }
        }
        float inv = 1.f / sum_ex;
        r_out[0] = fmaxf(fmaf(acc[0], inv, b0.x), 0.f);
        r_out[1] = fmaxf(fmaf(acc[1], inv, b0.y), 0.f);
        r_out[2] = fmaxf(fmaf(acc[2], inv, b0.z), 0.f);
        r_out[3] = fmaxf(fmaf(acc[3], inv, b0.w), 0.f);
        r_out[4] = fmaxf(fmaf(acc[4], inv, b1.x), 0.f);
        r_out[5] = fmaxf(fmaf(acc[5], inv, b1.y), 0.f);
        r_out[6] = fmaxf(fmaf(acc[6], inv, b1.z), 0.f);
        r_out[7] = fmaxf(fmaf(acc[7], inv, b1.w), 0.f);
    }
    if (POOL) {
        int grp = batch[w];
        float4* pp = (float4*)(g_psum + grp * FEAT + ch);
        atomicAdd(pp,     make_float4(r_out[0], r_out[1], r_out[2], r_out[3]));
        atomicAdd(pp + 1, make_float4(r_out[4], r_out[5], r_out[6], r_out[7]));
    } else {
        float4* op = (float4*)(out + (size_t)w * FEAT + ch);
        op[0] = make_float4(r_out[0], r_out[1], r_out[2], r_out[3]);
        op[1] = make_float4(r_out[4], r_out[5], r_out[6], r_out[7]);
    }
}

// ================= fc ======================================================
__global__ void fc_out(const float* __restrict__ Wfc, const float* __restrict__ bfc,
                       float* __restrict__ out) {
    int g = blockIdx.x, c = threadIdx.x;
    __shared__ float p[FEAT];
    float inv = 1.f / fmaxf(g_cnt[g], 1.f);
    p[c] = g_psum[g * FEAT + c] * inv;
    __syncthreads();
    float acc = bfc[c];
#pragma unroll 8
    for (int k = 0; k < FEAT; k++) acc = fmaf(p[k], Wfc[k * FEAT + c], acc);
    out[g * FEAT + c] = fmaxf(acc, 0.f);
}

// ================= launch =================================================
extern "C" void kernel_launch(void* const* d_in, const int* in_sizes, int n_in,
                              void* d_out, int out_size) {
    const float* x        = (const float*)d_in[0];
    const int*   ei       = (const int*)  d_in[1];
    const int*   batch    = (const int*)  d_in[2];
    const float* W1       = (const float*)d_in[3];
    const float* att_src1 = (const float*)d_in[4];
    const float* att_dst1 = (const float*)d_in[5];
    const float* b1       = (const float*)d_in[6];
    const float* W2       = (const float*)d_in[7];
    const float* att_src2 = (const float*)d_in[8];
    const float* att_dst2 = (const float*)d_in[9];
    const float* b2       = (const float*)d_in[10];
    const float* Wfc      = (const float*)d_in[11];
    const float* bfc      = (const float*)d_in[12];
    float* out = (float*)d_out;

    const int* src = ei;
    const int* dst = ei + N_EDGES;

    float *pB, *pas1, *pad1, *pas2, *pad2;
    __half* ph;
    __nv_bfloat16 *w1h, *w1l, *w2h, *w2l;
    cudaGetSymbolAddress((void**)&pB, g_bufB);
    cudaGetSymbolAddress((void**)&ph, g_h16);
    cudaGetSymbolAddress((void**)&pas1, g_asrc);
    cudaGetSymbolAddress((void**)&pad1, g_adst);
    cudaGetSymbolAddress((void**)&pas2, g_asrc2);
    cudaGetSymbolAddress((void**)&pad2, g_adst2);
    cudaGetSymbolAddress((void**)&w1h, g_w1h);
    cudaGetSymbolAddress((void**)&w1l, g_w1l);
    cudaGetSymbolAddress((void**)&w2h, g_w2h);
    cudaGetSymbolAddress((void**)&w2l, g_w2l);

    const int DYN_SM = 131072;
    cudaFuncSetAttribute(gemm_mma<HEADS>, cudaFuncAttributeMaxDynamicSharedMemorySize, DYN_SM);
    cudaFuncSetAttribute(gemm_mma<1>,     cudaFuncAttributeMaxDynamicSharedMemorySize, DYN_SM);

    static cudaStream_t s_side = nullptr;
    static cudaEvent_t evFork = nullptr, evJoin = nullptr;
    if (s_side == nullptr) {
        cudaStreamCreateWithFlags(&s_side, cudaStreamNonBlocking);
        cudaEventCreateWithFlags(&evFork, cudaEventDisableTiming);
        cudaEventCreateWithFlags(&evJoin, cudaEventDisableTiming);
    }

    int eBlocks    = (N_EDGES + 255) / 256;               // 3125
    int nhBlocks   = (N_NODES * HEADS + 255) / 256;       // 782
    int warpBlocks = (N_NODES * 32 + 255) / 256;          // 6250
    int nBlocks    = (N_NODES + 255) / 256;               // 196
    dim3 gemmGrid(2, (N_NODES + 127) / 128);              // (2, 391)

    // ---- init (main stream), then fork CSR build onto side stream ----
    zero_misc<<<nhBlocks, 256>>>();
    cudaEventRecord(evFork, 0);
    cudaStreamWaitEvent(s_side, evFork, 0);
    hist_plus<<<eBlocks, 256, 0, s_side>>>(dst, batch);
    scan1<<<nBlocks, 256, 0, s_side>>>();
    scan2<<<1, 256, 0, s_side>>>(nBlocks);
    scan3<<<nBlocks, 256, 0, s_side>>>();
    scatter<<<eBlocks, 256, 0, s_side>>>(src, dst);
    cudaEventRecord(evJoin, s_side);

    // ---- main stream: weights + GEMM1 (overlaps CSR build) ----
    conv_w2<<<512, 256>>>(W1, W2);
    gemm_mma<HEADS><<<gemmGrid, 256, DYN_SM>>>(x, w1h, w1l, ph, N_NODES,
                                               att_src1, att_dst1, pas1, pad1);

    // ---- join: gather needs CSR ----
    cudaStreamWaitEvent(0, evJoin, 0);
    gat_gather<HEADS, false><<<warpBlocks, 256>>>(ph, pB, b1, pas1, pad1, batch);

    // ---- layer 2 (gather fuses mean-pool accumulation) ----
    gemm_mma<1><<<gemmGrid, 256, DYN_SM>>>(pB, w2h, w2l, ph, N_NODES,
                                           att_src2, att_dst2, pas2, pad2);
    gat_gather<1, true><<<warpBlocks, 256>>>(ph, nullptr, b2, pas2, pad2, batch);

    // ---- fc ----
    fc_out<<<N_GRAPHS, FEAT>>>(Wfc, bfc, out);
}

// round 16
// speedup vs baseline: 1.6645x; 1.6645x over previous
#include <cuda_runtime.h>
#include <cuda_bf16.h>
#include <cuda_fp16.h>
#include <cstdint>

// ---------------- problem constants ----------------
#define N_NODES 50000
#define N_EDGES 800000
#define HEADS   4
#define N_GRAPHS 50
#define NEG_SLOPE 0.2f
#define FEAT 256

// ---------------- scratch ----------------
__device__ __half   g_h16 [N_NODES * FEAT];   // h1, then h2 (fp16 gather payload)
__device__ __half   g_o16 [N_NODES * FEAT];   // out1, then out2 (fp16)
__device__ float    g_asrc[N_NODES * HEADS];  // layer-1 scores
__device__ float    g_adst[N_NODES * HEADS];
__device__ float    g_asrc2[N_NODES];         // layer-2 scores (H=1)
__device__ float    g_adst2[N_NODES];
__device__ unsigned g_deg [N_NODES];
__device__ unsigned g_rowptr[N_NODES + 1];
__device__ unsigned g_cursor[N_NODES];
__device__ int      g_csrc[N_EDGES];
__device__ unsigned g_bsum[256];
__device__ float    g_psum[N_GRAPHS * FEAT];
__device__ float    g_cnt [N_GRAPHS];
__device__ __nv_bfloat16 g_w1h[FEAT * FEAT], g_w1l[FEAT * FEAT];
__device__ __nv_bfloat16 g_w2h[FEAT * FEAT], g_w2l[FEAT * FEAT];

// ---------------- helpers ----------------
__device__ __forceinline__ float lrelu(float v) { return v >= 0.f ? v : NEG_SLOPE * v; }
__device__ __forceinline__ uint32_t pack_bf2(float a, float b) {
    uint32_t lo = (uint32_t)__bfloat16_as_ushort(__float2bfloat16(a));
    uint32_t hi = (uint32_t)__bfloat16_as_ushort(__float2bfloat16(b));
    return (hi << 16) | lo;
}

// ================= weight convert (both layers, one kernel) ===============
__global__ void conv_w2(const float* __restrict__ W1, const float* __restrict__ W2) {
    int i = blockIdx.x * 256 + threadIdx.x;          // 0..131071
    int j = i & 65535;
    int k = j >> 8, n = j & 255;
    if (i < 65536) {
        float v = W1[j];
        __nv_bfloat16 h = __float2bfloat16(v);
        g_w1h[n * 256 + k] = h;
        g_w1l[n * 256 + k] = __float2bfloat16(v - __bfloat162float(h));
    } else {
        float v = W2[j];
        __nv_bfloat16 h = __float2bfloat16(v);
        g_w2h[n * 256 + k] = h;
        g_w2l[n * 256 + k] = __float2bfloat16(v - __bfloat162float(h));
    }
}

// ================= HMMA GEMM + fused attention-score epilogue =============
// A16=false: A is fp32; A16=true: A is fp16 (bf16 hi/lo split still ~exact).
__device__ __forceinline__ void mma16816(float* c, const uint32_t* a, const uint32_t* b) {
    asm volatile(
        "mma.sync.aligned.m16n8k16.row.col.f32.bf16.bf16.f32 "
        "{%0,%1,%2,%3}, {%4,%5,%6,%7}, {%8,%9}, {%0,%1,%2,%3};"
        : "+f"(c[0]), "+f"(c[1]), "+f"(c[2]), "+f"(c[3])
        : "r"(a[0]), "r"(a[1]), "r"(a[2]), "r"(a[3]), "r"(b[0]), "r"(b[1]));
}

template <int H, bool A16>
__global__ void __launch_bounds__(256, 1) gemm_mma(
    const void* __restrict__ Ain, const __nv_bfloat16* __restrict__ Bh,
    const __nv_bfloat16* __restrict__ Bl, __half* __restrict__ C, int M,
    const float* __restrict__ att_s, const float* __restrict__ att_d,
    float* __restrict__ o_asrc, float* __restrict__ o_adst) {
    extern __shared__ char sm[];
    uint32_t* Ahs = (uint32_t*)sm;                 // 64 KB
    uint32_t* Als = (uint32_t*)(sm + 65536);       // 64 KB

    int t = threadIdx.x;
    int warp = t >> 5, lane = t & 31;
    int g = lane >> 2, tg = lane & 3;
    int m0 = blockIdx.y * 128;
    int n0 = blockIdx.x * 128;

    // ---- stage A (fragment-permuted bf16 hi/lo) ----
    {
        int r0 = m0 + warp * 16 + g;
        int r1 = r0 + 8;
        bool ok0 = r0 < M, ok1 = r1 < M;
#pragma unroll
        for (int ks = 0; ks < 16; ks++) {
            float2 f0, f1, f2, f3;
            if constexpr (A16) {
                const __half* A0 = (const __half*)Ain + (size_t)r0 * 256 + 2 * tg;
                const __half* A1 = (const __half*)Ain + (size_t)r1 * 256 + 2 * tg;
                __half2 z = __floats2half2_rn(0.f, 0.f);
                f0 = __half22float2(ok0 ? *(const __half2*)(A0 + 16 * ks)     : z);
                f1 = __half22float2(ok1 ? *(const __half2*)(A1 + 16 * ks)     : z);
                f2 = __half22float2(ok0 ? *(const __half2*)(A0 + 16 * ks + 8) : z);
                f3 = __half22float2(ok1 ? *(const __half2*)(A1 + 16 * ks + 8) : z);
            } else {
                const float* A0 = (const float*)Ain + (size_t)r0 * 256 + 2 * tg;
                const float* A1 = (const float*)Ain + (size_t)r1 * 256 + 2 * tg;
                f0 = ok0 ? *(const float2*)(A0 + 16 * ks)     : make_float2(0.f, 0.f);
                f1 = ok1 ? *(const float2*)(A1 + 16 * ks)     : make_float2(0.f, 0.f);
                f2 = ok0 ? *(const float2*)(A0 + 16 * ks + 8) : make_float2(0.f, 0.f);
                f3 = ok1 ? *(const float2*)(A1 + 16 * ks + 8) : make_float2(0.f, 0.f);
            }
            float h0x = __bfloat162float(__float2bfloat16(f0.x));
            float h0y = __bfloat162float(__float2bfloat16(f0.y));
            float h1x = __bfloat162float(__float2bfloat16(f1.x));
            float h1y = __bfloat162float(__float2bfloat16(f1.y));
            float h2x = __bfloat162float(__float2bfloat16(f2.x));
            float h2y = __bfloat162float(__float2bfloat16(f2.y));
            float h3x = __bfloat162float(__float2bfloat16(f3.x));
            float h3y = __bfloat162float(__float2bfloat16(f3.y));
            int idx = ((warp * 16 + ks) * 32 + lane) * 4;
            uint4 hv = make_uint4(pack_bf2(f0.x, f0.y), pack_bf2(f1.x, f1.y),
                                  pack_bf2(f2.x, f2.y), pack_bf2(f3.x, f3.y));
            uint4 lv = make_uint4(pack_bf2(f0.x - h0x, f0.y - h0y),
                                  pack_bf2(f1.x - h1x, f1.y - h1y),
                                  pack_bf2(f2.x - h2x, f2.y - h2y),
                                  pack_bf2(f3.x - h3x, f3.y - h3y));
            *(uint4*)(Ahs + idx) = hv;
            *(uint4*)(Als + idx) = lv;
        }
    }
    __syncthreads();

    // ---- mainloop ----
    int wm = warp & 1;
    int wn = warp >> 1;
    float acc[4][4][4];
#pragma unroll
    for (int i = 0; i < 4; i++)
#pragma unroll
        for (int j = 0; j < 4; j++)
#pragma unroll
            for (int q = 0; q < 4; q++) acc[i][j][q] = 0.f;

    const __nv_bfloat16* Bbase[3] = { Bh, Bl, Bh };
#pragma unroll
    for (int pass = 0; pass < 3; pass++) {
        const uint32_t* Asm = (pass == 2) ? Als : Ahs;
        const __nv_bfloat16* Bg = Bbase[pass];
#pragma unroll 4
        for (int ks = 0; ks < 16; ks++) {
            uint32_t b[4][2];
#pragma unroll
            for (int fn = 0; fn < 4; fn++) {
                int n = n0 + wn * 32 + fn * 8 + g;
                const uint32_t* bp = (const uint32_t*)(Bg + (size_t)n * 256 + 16 * ks + 2 * tg);
                b[fn][0] = bp[0];
                b[fn][1] = bp[4];
            }
#pragma unroll
            for (int fm = 0; fm < 4; fm++) {
                int fm_g = wm * 4 + fm;
                uint4 av = *(const uint4*)(Asm + ((fm_g * 16 + ks) * 32 + lane) * 4);
                uint32_t a[4] = { av.x, av.y, av.z, av.w };
#pragma unroll
                for (int fn = 0; fn < 4; fn++)
                    mma16816(acc[fm][fn], a, b[fn]);
            }
        }
    }

    // ---- epilogue: store C as fp16 ----
#pragma unroll
    for (int fm = 0; fm < 4; fm++) {
        int r0 = m0 + wm * 64 + fm * 16 + g;
        int r1 = r0 + 8;
#pragma unroll
        for (int fn = 0; fn < 4; fn++) {
            int col = n0 + wn * 32 + fn * 8 + 2 * tg;
            if (r0 < M)
                *(__half2*)(C + (size_t)r0 * 256 + col) =
                    __floats2half2_rn(acc[fm][fn][0], acc[fm][fn][1]);
            if (r1 < M)
                *(__half2*)(C + (size_t)r1 * 256 + col) =
                    __floats2half2_rn(acc[fm][fn][2], acc[fm][fn][3]);
        }
    }

    // ---- epilogue: fused attention scores (fp32 accumulators) ----
    float2 as2[4], ad2[4];
#pragma unroll
    for (int fn = 0; fn < 4; fn++) {
        int col = n0 + wn * 32 + fn * 8 + 2 * tg;
        as2[fn] = *(const float2*)(att_s + col);
        ad2[fn] = *(const float2*)(att_d + col);
    }
    int head = (H == 4) ? ((n0 + wn * 32) >> 6) : 0;
#pragma unroll
    for (int fm = 0; fm < 4; fm++) {
        int r0 = m0 + wm * 64 + fm * 16 + g;
        int r1 = r0 + 8;
        float s0 = 0.f, d0 = 0.f, s1 = 0.f, d1 = 0.f;
#pragma unroll
        for (int fn = 0; fn < 4; fn++) {
            s0 += acc[fm][fn][0] * as2[fn].x + acc[fm][fn][1] * as2[fn].y;
            d0 += acc[fm][fn][0] * ad2[fn].x + acc[fm][fn][1] * ad2[fn].y;
            s1 += acc[fm][fn][2] * as2[fn].x + acc[fm][fn][3] * as2[fn].y;
            d1 += acc[fm][fn][2] * ad2[fn].x + acc[fm][fn][3] * ad2[fn].y;
        }
#pragma unroll
        for (int o = 1; o <= 2; o <<= 1) {
            s0 += __shfl_xor_sync(0xffffffffu, s0, o);
            d0 += __shfl_xor_sync(0xffffffffu, d0, o);
            s1 += __shfl_xor_sync(0xffffffffu, s1, o);
            d1 += __shfl_xor_sync(0xffffffffu, d1, o);
        }
        if (tg == 0) {
            if (r0 < M) {
                atomicAdd(&o_asrc[r0 * H + head], s0);
                atomicAdd(&o_adst[r0 * H + head], d0);
            }
            if (r1 < M) {
                atomicAdd(&o_asrc[r1 * H + head], s1);
                atomicAdd(&o_adst[r1 * H + head], d1);
            }
        }
    }
}

// ================= CSR build ==============================================
__global__ void zero_misc() {
    int i = blockIdx.x * 256 + threadIdx.x;
    if (i < N_NODES) { g_deg[i] = 0u; g_asrc2[i] = 0.f; g_adst2[i] = 0.f; }
    if (i < N_NODES * HEADS) { g_asrc[i] = 0.f; g_adst[i] = 0.f; }
    if (i < N_GRAPHS * FEAT) g_psum[i] = 0.f;
    if (i < N_GRAPHS) g_cnt[i] = 0.f;
}
__global__ void hist_plus(const int* __restrict__ dst, const int* __restrict__ batch) {
    int i = blockIdx.x * 256 + threadIdx.x;
    if (i < N_EDGES) atomicAdd(&g_deg[dst[i]], 1u);
    if (i < N_NODES) atomicAdd(&g_cnt[batch[i]], 1.0f);
}
__global__ void scan1() {
    __shared__ unsigned s[256];
    int t = threadIdx.x, i = blockIdx.x * 256 + t;
    unsigned v = (i < N_NODES) ? g_deg[i] : 0u;
    s[t] = v; __syncthreads();
#pragma unroll
    for (int o = 1; o < 256; o <<= 1) {
        unsigned u = (t >= o) ? s[t - o] : 0u;
        __syncthreads();
        s[t] += u; __syncthreads();
    }
    if (i < N_NODES) g_rowptr[i + 1] = s[t];
    if (t == 255) g_bsum[blockIdx.x] = s[255];
}
__global__ void scan2(int nb) {
    __shared__ unsigned s[256];
    int t = threadIdx.x;
    unsigned v = (t < nb) ? g_bsum[t] : 0u;
    s[t] = v; __syncthreads();
#pragma unroll
    for (int o = 1; o < 256; o <<= 1) {
        unsigned u = (t >= o) ? s[t - o] : 0u;
        __syncthreads();
        s[t] += u; __syncthreads();
    }
    if (t < nb) g_bsum[t] = s[t] - v;                // exclusive
}
__global__ void scan3() {
    int i = blockIdx.x * 256 + threadIdx.x;
    if (i >= N_NODES) return;
    unsigned f = g_rowptr[i + 1] + g_bsum[i >> 8];
    g_rowptr[i + 1] = f;
    g_cursor[i] = f - g_deg[i];
    if (i == 0) g_rowptr[0] = 0u;
}
__global__ void scatter(const int* __restrict__ src, const int* __restrict__ dst) {
    int e = blockIdx.x * 256 + threadIdx.x;
    if (e >= N_EDGES) return;
    unsigned p = atomicAdd(&g_cursor[dst[e]], 1u);
    g_csrc[p] = src[e];
}

// ================= fused single-pass GAT aggregation ======================
// out[w] = relu( (sum_e ex_e * h[src_e]) / (sum_e ex_e) + bias ), fp16 output.
// 2-edge unrolled (MLP=2) — the proven 486us configuration.
template <int H>
__global__ void gat_gather(const __half* __restrict__ h, __half* __restrict__ out,
                           const float* __restrict__ bias,
                           const float* __restrict__ v_asrc,
                           const float* __restrict__ v_adst) {
    int w = (blockIdx.x * blockDim.x + threadIdx.x) >> 5;
    int lane = threadIdx.x & 31;
    if (w >= N_NODES) return;
    int r0 = (int)g_rowptr[w], r1 = (int)g_rowptr[w + 1];
    int ch = lane * 8;
    int hh = (H == 4) ? (lane >> 3) : 0;
    float4 b0 = *(const float4*)(bias + ch);
    float4 b1 = *(const float4*)(bias + ch + 4);
    float r_out[8];
    if (r0 == r1) {
        r_out[0] = fmaxf(b0.x, 0.f); r_out[1] = fmaxf(b0.y, 0.f);
        r_out[2] = fmaxf(b0.z, 0.f); r_out[3] = fmaxf(b0.w, 0.f);
        r_out[4] = fmaxf(b1.x, 0.f); r_out[5] = fmaxf(b1.y, 0.f);
        r_out[6] = fmaxf(b1.z, 0.f); r_out[7] = fmaxf(b1.w, 0.f);
    } else {
        float ad_h = v_adst[w * H + hh];
        float acc[8];
#pragma unroll
        for (int q = 0; q < 8; q++) acc[q] = 0.f;
        float sum_ex = 0.f;
        int e = r0;
        for (; e + 1 < r1; e += 2) {
            int sA = g_csrc[e], sB = g_csrc[e + 1];
            float aA = v_asrc[sA * H + hh];
            float aB = v_asrc[sB * H + hh];
            uint4 vA = *(const uint4*)(h + (size_t)sA * FEAT + ch);
            uint4 vB = *(const uint4*)(h + (size_t)sB * FEAT + ch);
            float exA = __expf(lrelu(aA + ad_h));
            float exB = __expf(lrelu(aB + ad_h));
            sum_ex += exA + exB;
            const __half2* hA = (const __half2*)&vA;
            const __half2* hB = (const __half2*)&vB;
#pragma unroll
            for (int q = 0; q < 4; q++) {
                float2 fA = __half22float2(hA[q]);
                float2 fB = __half22float2(hB[q]);
                acc[2 * q + 0] = fmaf(exA, fA.x, fmaf(exB, fB.x, acc[2 * q + 0]));
                acc[2 * q + 1] = fmaf(exA, fA.y, fmaf(exB, fB.y, acc[2 * q + 1]));
            }
        }
        if (e < r1) {
            int s = g_csrc[e];
            float ex = __expf(lrelu(v_asrc[s * H + hh] + ad_h));
            sum_ex += ex;
            uint4 v = *(const uint4*)(h + (size_t)s * FEAT + ch);
            const __half2* hv = (const __half2*)&v;
#pragma unroll
            for (int q = 0; q < 4; q++) {
                float2 f = __half22float2(hv[q]);
                acc[2 * q + 0] = fmaf(ex, f.x, acc[2 * q + 0]);
                acc[2 * q + 1] = fmaf(ex, f.y, acc[2 * q + 1]);
            }
        }
        float inv = 1.f / sum_ex;
        r_out[0] = fmaxf(fmaf(acc[0], inv, b0.x), 0.f);
        r_out[1] = fmaxf(fmaf(acc[1], inv, b0.y), 0.f);
        r_out[2] = fmaxf(fmaf(acc[2], inv, b0.z), 0.f);
        r_out[3] = fmaxf(fmaf(acc[3], inv, b0.w), 0.f);
        r_out[4] = fmaxf(fmaf(acc[4], inv, b1.x), 0.f);
        r_out[5] = fmaxf(fmaf(acc[5], inv, b1.y), 0.f);
        r_out[6] = fmaxf(fmaf(acc[6], inv, b1.z), 0.f);
        r_out[7] = fmaxf(fmaf(acc[7], inv, b1.w), 0.f);
    }
    // single 16-byte fp16 store
    uint4 ov;
    __half2* op2 = (__half2*)&ov;
    op2[0] = __floats2half2_rn(r_out[0], r_out[1]);
    op2[1] = __floats2half2_rn(r_out[2], r_out[3]);
    op2[2] = __floats2half2_rn(r_out[4], r_out[5]);
    op2[3] = __floats2half2_rn(r_out[6], r_out[7]);
    *(uint4*)(out + (size_t)w * FEAT + ch) = ov;
}

// ================= pooling + fc ===========================================
#define NPB 128
__global__ void pool_sum(const __half* __restrict__ out2, const int* __restrict__ batch) {
    int c = threadIdx.x;
    int n0 = blockIdx.x * NPB;
    int n1 = n0 + NPB; if (n1 > N_NODES) n1 = N_NODES;
    if (n0 >= N_NODES) return;
    float acc = 0.f;
    int curg = batch[n0];
    for (int n = n0; n < n1; n++) {
        int g = batch[n];
        if (g != curg) { atomicAdd(&g_psum[curg * FEAT + c], acc); acc = 0.f; curg = g; }
        acc += __half2float(out2[(size_t)n * FEAT + c]);
    }
    atomicAdd(&g_psum[curg * FEAT + c], acc);
}
__global__ void fc_out(const float* __restrict__ Wfc, const float* __restrict__ bfc,
                       float* __restrict__ out) {
    int g = blockIdx.x, c = threadIdx.x;
    __shared__ float p[FEAT];
    float inv = 1.f / fmaxf(g_cnt[g], 1.f);
    p[c] = g_psum[g * FEAT + c] * inv;
    __syncthreads();
    float acc = bfc[c];
#pragma unroll 8
    for (int k = 0; k < FEAT; k++) acc = fmaf(p[k], Wfc[k * FEAT + c], acc);
    out[g * FEAT + c] = fmaxf(acc, 0.f);
}

// ================= launch =================================================
extern "C" void kernel_launch(void* const* d_in, const int* in_sizes, int n_in,
                              void* d_out, int out_size) {
    const float* x        = (const float*)d_in[0];
    const int*   ei       = (const int*)  d_in[1];
    const int*   batch    = (const int*)  d_in[2];
    const float* W1       = (const float*)d_in[3];
    const float* att_src1 = (const float*)d_in[4];
    const float* att_dst1 = (const float*)d_in[5];
    const float* b1       = (const float*)d_in[6];
    const float* W2       = (const float*)d_in[7];
    const float* att_src2 = (const float*)d_in[8];
    const float* att_dst2 = (const float*)d_in[9];
    const float* b2       = (const float*)d_in[10];
    const float* Wfc      = (const float*)d_in[11];
    const float* bfc      = (const float*)d_in[12];
    float* out = (float*)d_out;

    const int* src = ei;
    const int* dst = ei + N_EDGES;

    float *pas1, *pad1, *pas2, *pad2;
    __half *ph, *po;
    __nv_bfloat16 *w1h, *w1l, *w2h, *w2l;
    cudaGetSymbolAddress((void**)&ph, g_h16);
    cudaGetSymbolAddress((void**)&po, g_o16);
    cudaGetSymbolAddress((void**)&pas1, g_asrc);
    cudaGetSymbolAddress((void**)&pad1, g_adst);
    cudaGetSymbolAddress((void**)&pas2, g_asrc2);
    cudaGetSymbolAddress((void**)&pad2, g_adst2);
    cudaGetSymbolAddress((void**)&w1h, g_w1h);
    cudaGetSymbolAddress((void**)&w1l, g_w1l);
    cudaGetSymbolAddress((void**)&w2h, g_w2h);
    cudaGetSymbolAddress((void**)&w2l, g_w2l);

    const int DYN_SM = 131072;
    cudaFuncSetAttribute(gemm_mma<HEADS, false>, cudaFuncAttributeMaxDynamicSharedMemorySize, DYN_SM);
    cudaFuncSetAttribute(gemm_mma<1, true>,      cudaFuncAttributeMaxDynamicSharedMemorySize, DYN_SM);

    static cudaStream_t s_side = nullptr;
    static cudaEvent_t evFork = nullptr, evJoin = nullptr;
    if (s_side == nullptr) {
        cudaStreamCreateWithFlags(&s_side, cudaStreamNonBlocking);
        cudaEventCreateWithFlags(&evFork, cudaEventDisableTiming);
        cudaEventCreateWithFlags(&evJoin, cudaEventDisableTiming);
    }

    int eBlocks    = (N_EDGES + 255) / 256;               // 3125
    int nhBlocks   = (N_NODES * HEADS + 255) / 256;       // 782
    int warpBlocks = (N_NODES * 32 + 255) / 256;          // 6250
    int nBlocks    = (N_NODES + 255) / 256;               // 196
    dim3 gemmGrid(2, (N_NODES + 127) / 128);              // (2, 391)

    // ---- init (main stream), then fork CSR build onto side stream ----
    zero_misc<<<nhBlocks, 256>>>();
    cudaEventRecord(evFork, 0);
    cudaStreamWaitEvent(s_side, evFork, 0);
    hist_plus<<<eBlocks, 256, 0, s_side>>>(dst, batch);
    scan1<<<nBlocks, 256, 0, s_side>>>();
    scan2<<<1, 256, 0, s_side>>>(nBlocks);
    scan3<<<nBlocks, 256, 0, s_side>>>();
    scatter<<<eBlocks, 256, 0, s_side>>>(src, dst);
    cudaEventRecord(evJoin, s_side);

    // ---- main stream: weights + GEMM1 (overlaps CSR build) ----
    conv_w2<<<512, 256>>>(W1, W2);
    gemm_mma<HEADS, false><<<gemmGrid, 256, DYN_SM>>>(x, w1h, w1l, ph, N_NODES,
                                                      att_src1, att_dst1, pas1, pad1);

    // ---- join: gather needs CSR ----
    cudaStreamWaitEvent(0, evJoin, 0);
    gat_gather<HEADS><<<warpBlocks, 256>>>(ph, po, b1, pas1, pad1);   // out1 fp16

    // ---- layer 2 (A read as fp16) ----
    gemm_mma<1, true><<<gemmGrid, 256, DYN_SM>>>(po, w2h, w2l, ph, N_NODES,
                                                 att_src2, att_dst2, pas2, pad2);
    gat_gather<1><<<warpBlocks, 256>>>(ph, po, b2, pas2, pad2);       // out2 fp16

    // ---- pool + fc ----
    pool_sum<<<(N_NODES + NPB - 1) / NPB, 256>>>(po, batch);
    fc_out<<<N_GRAPHS, FEAT>>>(Wfc, bfc, out);
}